// round 1
// baseline (speedup 1.0000x reference)
#include <cuda_runtime.h>

// Correlation layer: out[b, di*9+dj, h, w] = sum_c f1[b,c,h,w] * f2[b,c,h+di-4,w+dj-4]
// B=8, C=256, H=64, W=128, R=4, D=81. All fp32.
//
// Decomposition:
//   grid = (H/4, B, 3)  -- blockIdx.z selects a group of 3 di values
//   block = (32, 4)     -- tx covers w in chunks of 4 (W_R=4), ty = h row in 4-row tile
//   Each thread keeps 3(di) x 9(dj) x 4(w) = 108 fp32 accumulators.
//   Channels processed in chunks of CC=4 with cp.async double buffering.
//   f2 halo rows staged in smem: 6 rows x 136 cols per channel, halos are
//   always out-of-image (block spans full W) -> zeroed once up front.

#define NB 8
#define NC 256
#define NH 64
#define NW 128
#define ND 81
#define CC 4
#define NCHUNK (NC / CC)
#define ROWS 6
#define ROWW 136   // 128 + 2*4 halo

__device__ __forceinline__ void cp_async16(void* sdst, const void* gsrc) {
    unsigned s = (unsigned)__cvta_generic_to_shared(sdst);
    asm volatile("cp.async.ca.shared.global [%0], [%1], 16;" :: "r"(s), "l"(gsrc));
}

__global__ void __launch_bounds__(128, 3)
corr_kernel(const float* __restrict__ f1, const float* __restrict__ f2,
            float* __restrict__ out)
{
    __shared__ float f2s[2][CC][ROWS][ROWW];

    const int tx = threadIdx.x;          // 0..31
    const int ty = threadIdx.y;          // 0..3
    const int tid = ty * 32 + tx;
    const int h0 = blockIdx.x * 4;
    const int b  = blockIdx.y;
    const int g  = blockIdx.z;           // di group: di_idx = 3g + i, i in 0..2
    const int h  = h0 + ty;
    const int w0 = tx * 4;
    const int rowbase = h0 + 3 * g - 4;  // global row of smem slot r=0

    // Zero all smem once. Valid row centers get overwritten every chunk;
    // invalid rows and the +-4 w halos stay zero for the whole kernel
    // (their validity is fixed per block).
    for (int i = tid; i < 2 * CC * ROWS * ROWW; i += 128)
        ((float*)f2s)[i] = 0.0f;
    __syncthreads();

    float acc[3][9][4];
    #pragma unroll
    for (int i = 0; i < 3; i++)
        #pragma unroll
        for (int j = 0; j < 9; j++)
            #pragma unroll
            for (int k = 0; k < 4; k++)
                acc[i][j][k] = 0.0f;

    // ---- cooperative loader: CC channels * 6 rows * 32 float4 = 768 tasks ----
    auto load_chunk = [&](int c0, int buf) {
        #pragma unroll
        for (int s = 0; s < (CC * ROWS * 32) / 128; s++) {   // 6 tasks/thread
            int t  = tid + 128 * s;
            int cc = t / (ROWS * 32);
            int r  = (t / 32) % ROWS;
            int q  = t % 32;                                  // float4 index in row
            int gr = rowbase + r;
            if (gr >= 0 && gr < NH) {
                const float* src = f2 + (((b * NC + c0 + cc) * NH + gr) * NW + 4 * q);
                cp_async16(&f2s[buf][cc][r][4 + 4 * q], src);
            }
        }
    };

    // ---- compute: per channel, 3 di rows, 12-float sliding window, 108 FMA ----
    auto compute_chunk = [&](int c0, int buf) {
        #pragma unroll
        for (int cc = 0; cc < CC; cc++) {
            const float4 f1v = *reinterpret_cast<const float4*>(
                f1 + (((b * NC + c0 + cc) * NH + h) * NW + w0));
            #pragma unroll
            for (int i = 0; i < 3; i++) {
                const float* row = &f2s[buf][cc][ty + i][0];
                float4 wa = *reinterpret_cast<const float4*>(row + w0);
                float4 wb = *reinterpret_cast<const float4*>(row + w0 + 4);
                float4 wc = *reinterpret_cast<const float4*>(row + w0 + 8);
                float win[12] = {wa.x, wa.y, wa.z, wa.w,
                                 wb.x, wb.y, wb.z, wb.w,
                                 wc.x, wc.y, wc.z, wc.w};
                #pragma unroll
                for (int j = 0; j < 9; j++) {
                    acc[i][j][0] += f1v.x * win[j];
                    acc[i][j][1] += f1v.y * win[j + 1];
                    acc[i][j][2] += f1v.z * win[j + 2];
                    acc[i][j][3] += f1v.w * win[j + 3];
                }
            }
        }
    };

    // ---- main loop: double-buffered cp.async pipeline ----
    load_chunk(0, 0);
    asm volatile("cp.async.commit_group;");
    for (int chunk = 0; chunk < NCHUNK; chunk++) {
        const int buf = chunk & 1;
        if (chunk + 1 < NCHUNK) {
            // buf^1 was last read in iteration chunk-1, which ended with
            // __syncthreads() -> safe to overwrite.
            load_chunk((chunk + 1) * CC, buf ^ 1);
            asm volatile("cp.async.commit_group;");
            asm volatile("cp.async.wait_group 1;");  // current buf's group done
        } else {
            asm volatile("cp.async.wait_group 0;");
        }
        __syncthreads();
        compute_chunk(chunk * CC, buf);
        __syncthreads();
    }

    // ---- epilogue: 27 float4 stores ----
    #pragma unroll
    for (int i = 0; i < 3; i++) {
        const int di = 3 * g + i;
        #pragma unroll
        for (int j = 0; j < 9; j++) {
            const int d = di * 9 + j;
            float4 v = make_float4(acc[i][j][0], acc[i][j][1],
                                   acc[i][j][2], acc[i][j][3]);
            *reinterpret_cast<float4*>(
                out + (((b * ND + d) * NH + h) * NW + w0)) = v;
        }
    }
}

extern "C" void kernel_launch(void* const* d_in, const int* in_sizes, int n_in,
                              void* d_out, int out_size) {
    const float* f1 = (const float*)d_in[0];
    const float* f2 = (const float*)d_in[1];
    float* out = (float*)d_out;
    dim3 grid(NH / 4, NB, 3);
    dim3 block(32, 4);
    corr_kernel<<<grid, block>>>(f1, f2, out);
}